// round 12
// baseline (speedup 1.0000x reference)
#include <cuda_runtime.h>
#include <cuda_fp16.h>
#include <cstdint>

// ---------------- problem constants ----------------
#define NB   8
#define C_   128
#define H_   96
#define W_   96
#define CO_  128
#define K2_  9
#define HW_  (H_ * W_)                 // 9216
#define NPIX 32                        // output pixels per CTA tile
#define NTILES_PER_IMG (HW_ / NPIX)    // 288
#define NCHUNK K2_                     // 9 chunks of K=128 (one per kernel tap)

// ---------------- smem layout (bytes) ----------------
#define SM_META_IDX  0                     // 288 * ushort4 = 2304
#define SM_META_WT   2304                  // 288 * uint2   = 2304
#define SM_B         4608                  // 2 x 8192 (fp16 [hh][px32][c64], SW128 per 4KB half)
#define SMEM_BYTES   (SM_B + 2 * 8192)     // 20992

// ---------------- device globals (no runtime alloc) ----------------
__device__ __align__(1024) __half g_xh[(size_t)NB * HW_ * C_];   // NHWC fp16
// A in mma-fragment order: 18 sub-chunks (k2*2+half), each 16KB:
// byte addr = sc*16384 + ((tile*4 + ks)*32 + lane)*16 + reg*4 + half16*2
__device__ __align__(1024) unsigned char g_wfrag[2 * K2_ * 16384];

// ---------------- helpers ----------------
__device__ __forceinline__ uint32_t smem_u32(const void* p) {
    uint32_t a;
    asm("{ .reg .u64 t; cvta.to.shared.u64 t, %1; cvt.u32.u64 %0, t; }" : "=r"(a) : "l"(p));
    return a;
}
#define SWZ128(o) ((o) ^ (((o) >> 3) & 0x70))

__device__ __forceinline__ void ldsm_x4(uint32_t& r0, uint32_t& r1,
                                        uint32_t& r2, uint32_t& r3, uint32_t addr) {
    asm volatile("ldmatrix.sync.aligned.m8n8.x4.shared.b16 {%0,%1,%2,%3}, [%4];"
                 : "=r"(r0), "=r"(r1), "=r"(r2), "=r"(r3) : "r"(addr));
}

__device__ __forceinline__ void hmma(float* d, const uint32_t* a, const uint32_t* b) {
    asm volatile(
        "mma.sync.aligned.m16n8k16.row.col.f32.f16.f16.f32 "
        "{%0,%1,%2,%3}, {%4,%5,%6,%7}, {%8,%9}, {%0,%1,%2,%3};"
        : "+f"(d[0]), "+f"(d[1]), "+f"(d[2]), "+f"(d[3])
        : "r"(a[0]), "r"(a[1]), "r"(a[2]), "r"(a[3]), "r"(b[0]), "r"(b[1]));
}

// ---------------- prep kernel: x transpose + weight fragment packing ----------------
#define TR_BLOCKS (NB * HW_ / 128)            // 576
#define W_BLOCKS  ((CO_ * C_ * K2_) / 2048)   // 36

__global__ __launch_bounds__(512)
void prep_kernel(const float* __restrict__ x, const float* __restrict__ w) {
    const int tid = threadIdx.x;
    if (blockIdx.x < TR_BLOCKS) {
        __shared__ __half ts[128][130];
        const int b   = blockIdx.x;
        const int n   = b / (HW_ / 128);
        const int hwb = (b % (HW_ / 128)) * 128;
#pragma unroll
        for (int i = tid; i < 128 * 32; i += 512) {
            int c   = i >> 5;
            int hw4 = (i & 31) << 2;
            float4 v = *(const float4*)(x + ((size_t)n * C_ + c) * HW_ + hwb + hw4);
            ts[hw4 + 0][c] = __float2half_rn(v.x);
            ts[hw4 + 1][c] = __float2half_rn(v.y);
            ts[hw4 + 2][c] = __float2half_rn(v.z);
            ts[hw4 + 3][c] = __float2half_rn(v.w);
        }
        __syncthreads();
#pragma unroll
        for (int i = tid; i < 128 * 16; i += 512) {
            int hw = i >> 4;
            int cg = (i & 15) << 3;
            uint4 r;
            r.x = *(const uint32_t*)&ts[hw][cg + 0];
            r.y = *(const uint32_t*)&ts[hw][cg + 2];
            r.z = *(const uint32_t*)&ts[hw][cg + 4];
            r.w = *(const uint32_t*)&ts[hw][cg + 6];
            *(uint4*)(g_xh + ((size_t)n * HW_ + hwb + hw) * C_ + cg) = r;
        }
    } else {
        int base = (blockIdx.x - TR_BLOCKS) * 2048;
#pragma unroll
        for (int t = 0; t < 4; t++) {
            int i = base + t * 512 + tid;          // i = (co*C + c)*9 + k2
            int k2 = i % K2_;
            int c  = (i / K2_) % C_;
            int co = i / (K2_ * C_);
            float v = w[i];
            int sc   = k2 * 2 + (c >> 6);
            int kk   = c & 63;
            int ks   = kk >> 4;
            int cl   = kk & 15;
            int tile = co >> 4;
            int r    = co & 15;
            int lane = ((r & 7) << 2) | ((cl >> 1) & 3);
            int reg  = ((cl >> 3) << 1) | ((r >> 3) & 1);
            uint32_t addr = (uint32_t)sc * 16384u
                          + (uint32_t)(((tile * 4 + ks) * 32 + lane) * 16 + reg * 4 + (cl & 1) * 2);
            *(__half*)(g_wfrag + addr) = __float2half_rn(v);
        }
    }
}

// ---------------- main kernel: 128 threads, 32-px tile, 5 CTAs/SM, K=128 chunks ----------------
__global__ __launch_bounds__(128, 5)
void deform_mma_kernel(const float* __restrict__ offset,
                       const float* __restrict__ mask,
                       const float* __restrict__ bias,
                       float* __restrict__ out) {
    extern __shared__ char smem[];
    uint32_t sb = smem_u32(smem);

    const int tid  = threadIdx.x;
    const int wid  = tid >> 5;
    const int lid  = tid & 31;
    const int tile = blockIdx.x;
    const int n    = tile / NTILES_PER_IMG;
    const int pbase = (tile % NTILES_PER_IMG) * NPIX;

    ushort4* sidx = (ushort4*)(smem + SM_META_IDX);
    uint2*   swtp = (uint2*)(smem + SM_META_WT);

    // --- phase 0: bilinear metadata per (k2, pixel) ---
    for (int i = tid; i < K2_ * NPIX; i += 128) {
        int k2 = i / NPIX;
        int p  = i % NPIX;
        int pg = pbase + p;
        int oy = pg / W_;
        int ox = pg % W_;

        float offY = offset[((size_t)(n * (2 * K2_) + 2 * k2)    ) * HW_ + pg];
        float offX = offset[((size_t)(n * (2 * K2_) + 2 * k2 + 1)) * HW_ + pg];
        float m    = mask  [((size_t)(n * K2_ + k2)) * HW_ + pg];

        int ky = k2 / 3, kx = k2 % 3;
        float py = (float)(oy - 1 + ky) + offY;
        float px = (float)(ox - 1 + kx) + offX;

        float y0f = floorf(py), x0f = floorf(px);
        float wy = py - y0f, wx = px - x0f;
        int y0 = (int)y0f, x0 = (int)x0f;
        int y1 = y0 + 1,   x1 = x0 + 1;

        bool vy0 = (y0 >= 0) & (y0 < H_);
        bool vy1 = (y1 >= 0) & (y1 < H_);
        bool vx0 = (x0 >= 0) & (x0 < W_);
        bool vx1 = (x1 >= 0) & (x1 < W_);

        int cy0 = min(max(y0, 0), H_ - 1);
        int cy1 = min(max(y1, 0), H_ - 1);
        int cx0 = min(max(x0, 0), W_ - 1);
        int cx1 = min(max(x1, 0), W_ - 1);

        ushort4 id;
        id.x = (unsigned short)(cy0 * W_ + cx0);
        id.y = (unsigned short)(cy0 * W_ + cx1);
        id.z = (unsigned short)(cy1 * W_ + cx0);
        id.w = (unsigned short)(cy1 * W_ + cx1);

        float w00 = (vy0 & vx0) ? (1.f - wy) * (1.f - wx) * m : 0.f;
        float w01 = (vy0 & vx1) ? (1.f - wy) * wx * m         : 0.f;
        float w10 = (vy1 & vx0) ? wy * (1.f - wx) * m         : 0.f;
        float w11 = (vy1 & vx1) ? wy * wx * m                 : 0.f;

        __half2 pa = __halves2half2(__float2half_rn(w00), __float2half_rn(w01));
        __half2 pb = __halves2half2(__float2half_rn(w10), __float2half_rn(w11));
        uint2 wp;
        wp.x = *(uint32_t*)&pa;
        wp.y = *(uint32_t*)&pb;
        sidx[i] = id;
        swtp[i] = wp;
    }

    const __half* xh_n = g_xh + (size_t)n * HW_ * C_;

    // gather thread mapping (CTA-banded): iteration it covers pixels it*8..it*8+7
    const int p_  = tid >> 4;          // pixel within band (stride 8 per iteration)
    const int gg  = tid & 15;          // 16 x 8-channel groups (both halves)
    const int hh_ = gg >> 3;           // channel half
    const int g8  = gg & 7;

    // --- register tile: warp = 32 co x 32 px ---
    const int t0  = wid * 2;           // first m16 tile index
    const int gid = lid >> 2;
    const int tig = lid & 3;

    float acc[2][4][4];
#pragma unroll
    for (int i = 0; i < 2; i++)
#pragma unroll
        for (int j = 0; j < 4; j++)
#pragma unroll
            for (int q = 0; q < 4; q++) acc[i][j][q] = 0.f;

    const int b_rowoff = ((lid >> 4) << 3) + (lid & 7);
    const int b_koff   = ((lid >> 3) & 1) << 4;

    __syncthreads();   // metadata visible

    // --- main loop over 9 K=128 chunks (double-buffered B, one sync per chunk) ---
    for (int ch = 0; ch < NCHUNK; ch++) {
        const int buf = ch & 1;

        // A fragments for first channel-half (sub-chunk 2*ch) — issue first
        uint4 af[2][4];
        {
            const uint4* abase = (const uint4*)(g_wfrag + (size_t)(2 * ch) * 16384);
#pragma unroll
            for (int t = 0; t < 2; t++)
#pragma unroll
                for (int ks = 0; ks < 4; ks++)
                    af[t][ks] = __ldg(abase + ((t0 + t) * 4 + ks) * 32 + lid);
        }

        // gather both halves of this tap: 4 iterations, CTA-contiguous pixel bands
        char* bbuf = smem + SM_B + buf * 8192;
        {
            const __half* base = xh_n + hh_ * 64 + g8 * 8;
            char* bsub = bbuf + hh_ * 4096;
#pragma unroll
            for (int it = 0; it < 4; it++) {
                int p = it * 8 + p_;
                int s = ch * NPIX + p;
                ushort4 id = sidx[s];
                uint2   wp = swtp[s];

                __half2 pa = *(__half2*)&wp.x;
                __half2 pb = *(__half2*)&wp.y;
                __half2 w00 = __half2half2(__low2half(pa));
                __half2 w01 = __half2half2(__high2half(pa));
                __half2 w10 = __half2half2(__low2half(pb));
                __half2 w11 = __half2half2(__high2half(pb));

                uint4 q0 = *(const uint4*)(base + ((uint32_t)id.x << 7));
                uint4 q1 = *(const uint4*)(base + ((uint32_t)id.y << 7));
                uint4 q2 = *(const uint4*)(base + ((uint32_t)id.z << 7));
                uint4 q3 = *(const uint4*)(base + ((uint32_t)id.w << 7));

                const __half2* h0 = (const __half2*)&q0;
                const __half2* h1 = (const __half2*)&q1;
                const __half2* h2 = (const __half2*)&q2;
                const __half2* h3 = (const __half2*)&q3;

                uint4 r;
                uint32_t* rp = (uint32_t*)&r;
#pragma unroll
                for (int j = 0; j < 4; j++) {
                    __half2 v = __hmul2(w00, h0[j]);
                    v = __hfma2(w01, h1[j], v);
                    v = __hfma2(w10, h2[j], v);
                    v = __hfma2(w11, h3[j], v);
                    rp[j] = *(uint32_t*)&v;
                }
                *(uint4*)(bsub + SWZ128((uint32_t)(p * 128 + g8 * 16))) = r;
            }
        }

        __syncthreads();

        // --- HMMA: two channel-halves, 4 ks each ---
#pragma unroll
        for (int half = 0; half < 2; half++) {
            if (half == 1) {
                // reload A for second half; latency hides under half-0 HMMA drain
                const uint4* abase = (const uint4*)(g_wfrag + (size_t)(2 * ch + 1) * 16384);
#pragma unroll
                for (int t = 0; t < 2; t++)
#pragma unroll
                    for (int ks = 0; ks < 4; ks++)
                        af[t][ks] = __ldg(abase + ((t0 + t) * 4 + ks) * 32 + lid);
            }
            const uint32_t b_base = sb + SM_B + buf * 8192 + half * 4096;
#pragma unroll
            for (int ks = 0; ks < 4; ks++) {
                uint32_t bfr[4][2];
#pragma unroll
                for (int m = 0; m < 2; m++) {
                    ldsm_x4(bfr[2 * m][0], bfr[2 * m][1], bfr[2 * m + 1][0], bfr[2 * m + 1][1],
                            b_base + SWZ128((uint32_t)((16 * m + b_rowoff) * 128 + ks * 32 + b_koff)));
                }
#pragma unroll
                for (int i = 0; i < 2; i++)
#pragma unroll
                    for (int j = 0; j < 4; j++)
                        hmma(acc[i][j], (const uint32_t*)&af[i][ks], bfr[j]);
            }
        }
        // buffer-reuse safety: writes to this buf (chunk ch+2) happen after
        // sync(ch+1), which every warp only passes after finishing MMA(ch).
    }

    // --- epilogue: bias + store ---
    const int co0 = wid * 32;
#pragma unroll
    for (int i = 0; i < 2; i++) {
        int coA = co0 + 16 * i + gid;
        float b0 = __ldg(bias + coA);
        float b1 = __ldg(bias + coA + 8);
        float* o0 = out + ((size_t)(n * CO_ + coA)) * HW_ + pbase;
        float* o1 = o0 + 8 * HW_;
#pragma unroll
        for (int j = 0; j < 4; j++) {
            int px = 8 * j + 2 * tig;
            float2 v0 = make_float2(acc[i][j][0] + b0, acc[i][j][1] + b0);
            float2 v1 = make_float2(acc[i][j][2] + b1, acc[i][j][3] + b1);
            *(float2*)(o0 + px) = v0;
            *(float2*)(o1 + px) = v1;
        }
    }
}

// ---------------- launch ----------------
extern "C" void kernel_launch(void* const* d_in, const int* in_sizes, int n_in,
                              void* d_out, int out_size) {
    const float* x      = (const float*)d_in[0];
    const float* offset = (const float*)d_in[1];
    const float* mask   = (const float*)d_in[2];
    const float* weight = (const float*)d_in[3];
    const float* bias   = (const float*)d_in[4];
    float* out = (float*)d_out;

    cudaFuncSetAttribute(deform_mma_kernel,
                         cudaFuncAttributeMaxDynamicSharedMemorySize, SMEM_BYTES);

    prep_kernel<<<TR_BLOCKS + W_BLOCKS, 512>>>(x, weight);
    deform_mma_kernel<<<NB * NTILES_PER_IMG, 128, SMEM_BYTES>>>(offset, mask, bias, out);
}

// round 13
// speedup vs baseline: 1.1173x; 1.1173x over previous
#include <cuda_runtime.h>
#include <cuda_fp16.h>
#include <cstdint>

// ---------------- problem constants ----------------
#define NB   8
#define C_   128
#define H_   96
#define W_   96
#define CO_  128
#define K2_  9
#define HW_  (H_ * W_)                 // 9216
#define NPIX 64                        // output pixels per CTA tile
#define NTILES_PER_IMG (HW_ / NPIX)    // 144
#define NCHUNK K2_                     // 9 chunks of K=128 (one per kernel tap)

// ---------------- smem layout (bytes) ----------------
#define SM_META_IDX  0                     // 576 * ushort4 = 4608
#define SM_META_WT   4608                  // 576 * uint2   = 4608
#define SM_B         9216                  // 2 x 16384 (fp16 [hh][px][c64], SW128 per 8KB half)
#define SMEM_BYTES   (SM_B + 2 * 16384)    // 41984

// ---------------- device globals (no runtime alloc) ----------------
__device__ __align__(1024) __half g_xh[(size_t)NB * HW_ * C_];   // NHWC fp16
// A in mma-fragment order: 18 sub-chunks (k2*2+half), each 16KB:
// byte addr = sc*16384 + ((tile*4 + ks)*32 + lane)*16 + reg*4 + half16*2
__device__ __align__(1024) unsigned char g_wfrag[2 * K2_ * 16384];

// ---------------- helpers ----------------
__device__ __forceinline__ uint32_t smem_u32(const void* p) {
    uint32_t a;
    asm("{ .reg .u64 t; cvta.to.shared.u64 t, %1; cvt.u32.u64 %0, t; }" : "=r"(a) : "l"(p));
    return a;
}
#define SWZ128(o) ((o) ^ (((o) >> 3) & 0x70))

__device__ __forceinline__ void ldsm_x4(uint32_t& r0, uint32_t& r1,
                                        uint32_t& r2, uint32_t& r3, uint32_t addr) {
    asm volatile("ldmatrix.sync.aligned.m8n8.x4.shared.b16 {%0,%1,%2,%3}, [%4];"
                 : "=r"(r0), "=r"(r1), "=r"(r2), "=r"(r3) : "r"(addr));
}

__device__ __forceinline__ void hmma(float* d, const uint32_t* a, const uint32_t* b) {
    asm volatile(
        "mma.sync.aligned.m16n8k16.row.col.f32.f16.f16.f32 "
        "{%0,%1,%2,%3}, {%4,%5,%6,%7}, {%8,%9}, {%0,%1,%2,%3};"
        : "+f"(d[0]), "+f"(d[1]), "+f"(d[2]), "+f"(d[3])
        : "r"(a[0]), "r"(a[1]), "r"(a[2]), "r"(a[3]), "r"(b[0]), "r"(b[1]));
}

// ---------------- prep kernel: x transpose + weight fragment packing ----------------
#define TR_BLOCKS (NB * HW_ / 128)            // 576
#define W_BLOCKS  ((CO_ * C_ * K2_) / 2048)   // 36

__global__ __launch_bounds__(512)
void prep_kernel(const float* __restrict__ x, const float* __restrict__ w) {
    const int tid = threadIdx.x;
    if (blockIdx.x < TR_BLOCKS) {
        __shared__ __half ts[128][130];
        const int b   = blockIdx.x;
        const int n   = b / (HW_ / 128);
        const int hwb = (b % (HW_ / 128)) * 128;
#pragma unroll
        for (int i = tid; i < 128 * 32; i += 512) {
            int c   = i >> 5;
            int hw4 = (i & 31) << 2;
            float4 v = *(const float4*)(x + ((size_t)n * C_ + c) * HW_ + hwb + hw4);
            ts[hw4 + 0][c] = __float2half_rn(v.x);
            ts[hw4 + 1][c] = __float2half_rn(v.y);
            ts[hw4 + 2][c] = __float2half_rn(v.z);
            ts[hw4 + 3][c] = __float2half_rn(v.w);
        }
        __syncthreads();
#pragma unroll
        for (int i = tid; i < 128 * 16; i += 512) {
            int hw = i >> 4;
            int cg = (i & 15) << 3;
            uint4 r;
            r.x = *(const uint32_t*)&ts[hw][cg + 0];
            r.y = *(const uint32_t*)&ts[hw][cg + 2];
            r.z = *(const uint32_t*)&ts[hw][cg + 4];
            r.w = *(const uint32_t*)&ts[hw][cg + 6];
            *(uint4*)(g_xh + ((size_t)n * HW_ + hwb + hw) * C_ + cg) = r;
        }
    } else {
        int base = (blockIdx.x - TR_BLOCKS) * 2048;
#pragma unroll
        for (int t = 0; t < 4; t++) {
            int i = base + t * 512 + tid;          // i = (co*C + c)*9 + k2
            int k2 = i % K2_;
            int c  = (i / K2_) % C_;
            int co = i / (K2_ * C_);
            float v = w[i];
            int sc   = k2 * 2 + (c >> 6);
            int kk   = c & 63;
            int ks   = kk >> 4;
            int cl   = kk & 15;
            int tile = co >> 4;
            int r    = co & 15;
            int lane = ((r & 7) << 2) | ((cl >> 1) & 3);
            int reg  = ((cl >> 3) << 1) | ((r >> 3) & 1);
            uint32_t addr = (uint32_t)sc * 16384u
                          + (uint32_t)(((tile * 4 + ks) * 32 + lane) * 16 + reg * 4 + (cl & 1) * 2);
            *(__half*)(g_wfrag + addr) = __float2half_rn(v);
        }
    }
}

// ---------------- main kernel: 128 threads, 64-px tile, 4 CTAs/SM ----------------
// Warp tile = 64co x 32px (2x2 warp grid) to halve B-LDSM amplification.
__global__ __launch_bounds__(128, 4)
void deform_mma_kernel(const float* __restrict__ offset,
                       const float* __restrict__ mask,
                       const float* __restrict__ bias,
                       float* __restrict__ out) {
    extern __shared__ char smem[];
    uint32_t sb = smem_u32(smem);

    const int tid  = threadIdx.x;
    const int wid  = tid >> 5;
    const int lid  = tid & 31;
    const int tile = blockIdx.x;
    const int n    = tile / NTILES_PER_IMG;
    const int pbase = (tile % NTILES_PER_IMG) * NPIX;

    ushort4* sidx = (ushort4*)(smem + SM_META_IDX);
    uint2*   swtp = (uint2*)(smem + SM_META_WT);

    // --- phase 0: bilinear metadata per (k2, pixel) ---
    for (int i = tid; i < K2_ * NPIX; i += 128) {
        int k2 = i / NPIX;
        int p  = i % NPIX;
        int pg = pbase + p;
        int oy = pg / W_;
        int ox = pg % W_;

        float offY = offset[((size_t)(n * (2 * K2_) + 2 * k2)    ) * HW_ + pg];
        float offX = offset[((size_t)(n * (2 * K2_) + 2 * k2 + 1)) * HW_ + pg];
        float m    = mask  [((size_t)(n * K2_ + k2)) * HW_ + pg];

        int ky = k2 / 3, kx = k2 % 3;
        float py = (float)(oy - 1 + ky) + offY;
        float px = (float)(ox - 1 + kx) + offX;

        float y0f = floorf(py), x0f = floorf(px);
        float wy = py - y0f, wx = px - x0f;
        int y0 = (int)y0f, x0 = (int)x0f;
        int y1 = y0 + 1,   x1 = x0 + 1;

        bool vy0 = (y0 >= 0) & (y0 < H_);
        bool vy1 = (y1 >= 0) & (y1 < H_);
        bool vx0 = (x0 >= 0) & (x0 < W_);
        bool vx1 = (x1 >= 0) & (x1 < W_);

        int cy0 = min(max(y0, 0), H_ - 1);
        int cy1 = min(max(y1, 0), H_ - 1);
        int cx0 = min(max(x0, 0), W_ - 1);
        int cx1 = min(max(x1, 0), W_ - 1);

        ushort4 id;
        id.x = (unsigned short)(cy0 * W_ + cx0);
        id.y = (unsigned short)(cy0 * W_ + cx1);
        id.z = (unsigned short)(cy1 * W_ + cx0);
        id.w = (unsigned short)(cy1 * W_ + cx1);

        float w00 = (vy0 & vx0) ? (1.f - wy) * (1.f - wx) * m : 0.f;
        float w01 = (vy0 & vx1) ? (1.f - wy) * wx * m         : 0.f;
        float w10 = (vy1 & vx0) ? wy * (1.f - wx) * m         : 0.f;
        float w11 = (vy1 & vx1) ? wy * wx * m                 : 0.f;

        __half2 pa = __halves2half2(__float2half_rn(w00), __float2half_rn(w01));
        __half2 pb = __halves2half2(__float2half_rn(w10), __float2half_rn(w11));
        uint2 wp;
        wp.x = *(uint32_t*)&pa;
        wp.y = *(uint32_t*)&pb;
        sidx[i] = id;
        swtp[i] = wp;
    }

    const __half* xh_n = g_xh + (size_t)n * HW_ * C_;

    // gather thread mapping (CTA-banded): iteration it covers pixels it*8..it*8+7
    const int p_  = tid >> 4;          // pixel within band (stride 8 per iteration)
    const int gg  = tid & 15;          // 16 x 8-channel groups (both halves)
    const int hh_ = gg >> 3;           // channel half
    const int g8  = gg & 7;

    // --- register tile: warp = 64 co x 32 px (2x2 warp grid) ---
    const int cohalf = wid & 1;        // co half: tiles t0..t0+3
    const int pxhalf = wid >> 1;       // px half: rows px0..px0+31
    const int t0  = cohalf * 4;        // first m16 tile index (4 tiles per warp)
    const int px0 = pxhalf * 32;
    const int gid = lid >> 2;
    const int tig = lid & 3;

    float acc[4][4][4];                // [m16 tile][n8 group][4]
#pragma unroll
    for (int i = 0; i < 4; i++)
#pragma unroll
        for (int j = 0; j < 4; j++)
#pragma unroll
            for (int q = 0; q < 4; q++) acc[i][j][q] = 0.f;

    const int b_rowoff = ((lid >> 4) << 3) + (lid & 7);
    const int b_koff   = ((lid >> 3) & 1) << 4;

    __syncthreads();   // metadata visible

    // --- main loop over 9 K=128 chunks (double-buffered B, one sync per chunk) ---
    for (int ch = 0; ch < NCHUNK; ch++) {
        const int buf = ch & 1;

        // A fragments: ks-pair 0 of first channel-half — issue before gather
        uint4 af[4][2];
        {
            const uint4* abase = (const uint4*)(g_wfrag + (size_t)(2 * ch) * 16384);
#pragma unroll
            for (int t = 0; t < 4; t++)
#pragma unroll
                for (int k = 0; k < 2; k++)
                    af[t][k] = __ldg(abase + ((t0 + t) * 4 + k) * 32 + lid);
        }

        // gather both halves of this tap: 8 iterations, CTA-contiguous pixel bands
        char* bbuf = smem + SM_B + buf * 16384;
        {
            const __half* base = xh_n + hh_ * 64 + g8 * 8;
            char* bsub = bbuf + hh_ * 8192;
#pragma unroll
            for (int it = 0; it < 8; it++) {
                int p = it * 8 + p_;
                int s = ch * NPIX + p;
                ushort4 id = sidx[s];
                uint2   wp = swtp[s];

                __half2 pa = *(__half2*)&wp.x;
                __half2 pb = *(__half2*)&wp.y;
                __half2 w00 = __half2half2(__low2half(pa));
                __half2 w01 = __half2half2(__high2half(pa));
                __half2 w10 = __half2half2(__low2half(pb));
                __half2 w11 = __half2half2(__high2half(pb));

                uint4 q0 = *(const uint4*)(base + ((uint32_t)id.x << 7));
                uint4 q1 = *(const uint4*)(base + ((uint32_t)id.y << 7));
                uint4 q2 = *(const uint4*)(base + ((uint32_t)id.z << 7));
                uint4 q3 = *(const uint4*)(base + ((uint32_t)id.w << 7));

                const __half2* h0 = (const __half2*)&q0;
                const __half2* h1 = (const __half2*)&q1;
                const __half2* h2 = (const __half2*)&q2;
                const __half2* h3 = (const __half2*)&q3;

                uint4 r;
                uint32_t* rp = (uint32_t*)&r;
#pragma unroll
                for (int j = 0; j < 4; j++) {
                    __half2 v = __hmul2(w00, h0[j]);
                    v = __hfma2(w01, h1[j], v);
                    v = __hfma2(w10, h2[j], v);
                    v = __hfma2(w11, h3[j], v);
                    rp[j] = *(uint32_t*)&v;
                }
                *(uint4*)(bsub + SWZ128((uint32_t)(p * 128 + g8 * 16))) = r;
            }
        }

        __syncthreads();

        // --- HMMA: two channel-halves; per half, two ks-pairs with A reloads ---
#pragma unroll
        for (int half = 0; half < 2; half++) {
            const uint4* abase = (const uint4*)(g_wfrag + (size_t)(2 * ch + half) * 16384);
            if (half == 1) {
                // ks-pair 0 of second half (latency hides under prior MMA drain)
#pragma unroll
                for (int t = 0; t < 4; t++)
#pragma unroll
                    for (int k = 0; k < 2; k++)
                        af[t][k] = __ldg(abase + ((t0 + t) * 4 + k) * 32 + lid);
            }
            const uint32_t b_base = sb + SM_B + buf * 16384 + half * 8192;
#pragma unroll
            for (int kp = 0; kp < 2; kp++) {
#pragma unroll
                for (int kk = 0; kk < 2; kk++) {
                    const int ks = kp * 2 + kk;
                    uint32_t bfr[4][2];
#pragma unroll
                    for (int m = 0; m < 2; m++) {
                        ldsm_x4(bfr[2 * m][0], bfr[2 * m][1], bfr[2 * m + 1][0], bfr[2 * m + 1][1],
                                b_base + SWZ128((uint32_t)((px0 + 16 * m + b_rowoff) * 128 + ks * 32 + b_koff)));
                    }
#pragma unroll
                    for (int i = 0; i < 4; i++)
#pragma unroll
                        for (int j = 0; j < 4; j++)
                            hmma(acc[i][j], (const uint32_t*)&af[i][kk], bfr[j]);
                }
                if (kp == 0) {
                    // reload A for ks-pair 1 of this half
#pragma unroll
                    for (int t = 0; t < 4; t++)
#pragma unroll
                        for (int k = 0; k < 2; k++)
                            af[t][k] = __ldg(abase + ((t0 + t) * 4 + 2 + k) * 32 + lid);
                }
            }
        }
        // buffer-reuse safety: writes to this buf (chunk ch+2) happen after
        // sync(ch+1), which every warp only passes after finishing MMA(ch).
    }

    // --- epilogue: bias + store ---
    const int co0 = cohalf * 64;
#pragma unroll
    for (int i = 0; i < 4; i++) {
        int coA = co0 + 16 * i + gid;
        float b0 = __ldg(bias + coA);
        float b1 = __ldg(bias + coA + 8);
        float* o0 = out + ((size_t)(n * CO_ + coA)) * HW_ + pbase + px0;
        float* o1 = o0 + 8 * HW_;
#pragma unroll
        for (int j = 0; j < 4; j++) {
            int px = 8 * j + 2 * tig;
            float2 v0 = make_float2(acc[i][j][0] + b0, acc[i][j][1] + b0);
            float2 v1 = make_float2(acc[i][j][2] + b1, acc[i][j][3] + b1);
            *(float2*)(o0 + px) = v0;
            *(float2*)(o1 + px) = v1;
        }
    }
}

// ---------------- launch ----------------
extern "C" void kernel_launch(void* const* d_in, const int* in_sizes, int n_in,
                              void* d_out, int out_size) {
    const float* x      = (const float*)d_in[0];
    const float* offset = (const float*)d_in[1];
    const float* mask   = (const float*)d_in[2];
    const float* weight = (const float*)d_in[3];
    const float* bias   = (const float*)d_in[4];
    float* out = (float*)d_out;

    cudaFuncSetAttribute(deform_mma_kernel,
                         cudaFuncAttributeMaxDynamicSharedMemorySize, SMEM_BYTES);

    prep_kernel<<<TR_BLOCKS + W_BLOCKS, 512>>>(x, weight);
    deform_mma_kernel<<<NB * NTILES_PER_IMG, 128, SMEM_BYTES>>>(offset, mask, bias, out);
}